// round 16
// baseline (speedup 1.0000x reference)
#include <cuda_runtime.h>
#include <cuda_fp16.h>
#include <cstdint>

#define CIN 192
#define COUT 192
#define NB 4

// device scratch (sanctioned no-alloc workaround)
__device__ __align__(256) __half g_xt[NB * 256 * 256 * CIN];  // pixel-major [b][h][w][cin]
__device__ __align__(256) __half g_wt[9 * COUT * CIN];        // [tap][cout][cin]
__device__ __align__(256) float g_valid[NB * 256 * 256];

// ---------------------------------------------------------------------------
// Pass 1a: fp32 x [b][cin][h][w] -> fp16, pixel-major [b][h][w][cin]
// ---------------------------------------------------------------------------
#define TPS 200
__global__ void __launch_bounds__(256) cvt_x_kernel(const float* __restrict__ x) {
    __shared__ __half s[64 * TPS];
    const int tid = threadIdx.x;
    const int w0 = blockIdx.x << 6, h = blockIdx.y, b = blockIdx.z;
    const int wloc = tid & 63, cg = tid >> 6;
    const float* xb = x + ((b * CIN) * 256 + h) * 256 + w0;
    for (int ci = cg; ci < CIN; ci += 4)
        s[wloc * TPS + ci] = __float2half_rn(xb[ci * 65536 + wloc]);
    __syncthreads();
    int pixbase = ((b * 256 + h) * 256 + w0) * CIN;
    uint4* d = (uint4*)(g_xt + pixbase);
    for (int j = tid; j < 64 * 24; j += 256) {
        int p = j / 24, c = j % 24;
        d[j] = *(const uint4*)(s + p * TPS + c * 8);
    }
}

// ---------------------------------------------------------------------------
// Pass 1b: weight [cout][cin][kh][kw] -> tap-major [tap][cout][cin] fp16
// ---------------------------------------------------------------------------
__global__ void cvt_w_kernel(const float* __restrict__ w) {
    int i = blockIdx.x * blockDim.x + threadIdx.x;
    if (i >= COUT * CIN * 9) return;
    int kw = i % 3, kh = (i / 3) % 3, ci = (i / 9) % CIN, co = i / (9 * CIN);
    g_wt[((kh * 3 + kw) * COUT + co) * CIN + ci] = __float2half_rn(w[i]);
}

// ---------------------------------------------------------------------------
// Pass 1c: validity = 3x3 "any mask != 0" pool
// ---------------------------------------------------------------------------
__global__ void valid_kernel(const int* __restrict__ mask) {
    int i = blockIdx.x * blockDim.x + threadIdx.x;
    if (i >= NB * 256 * 256) return;
    int b = i >> 16, y = (i >> 8) & 255, x = i & 255;
    const int* mb = mask + (b << 16);
    int v = 0;
#pragma unroll
    for (int dy = -1; dy <= 1; ++dy) {
        int yy = y + dy;
        if (yy < 0 || yy > 255) continue;
#pragma unroll
        for (int dx = -1; dx <= 1; ++dx) {
            int xx = x + dx;
            if (xx < 0 || xx > 255) continue;
            v |= mb[yy * 256 + xx];
        }
    }
    g_valid[i] = (v != 0) ? 1.0f : 0.0f;
}

// ---------------------------------------------------------------------------
// Pass 2: implicit-GEMM conv, fp16 mma.sync m16n8k16, single pass.
// CTA = 64 cout x 4 output rows x 256 px, 512 threads (16 warps), 1 CTA/SM.
// wr = warp>>2 (output row 0..3), wc = warp&3 (64-px quarter).
// Warp tile 64 cout x 64 px: acc[4][8][4], 4:1 mma:LDSM4 ratio.
// Paired-B ldmatrix.x4 (2 nf per load). Double-buffered cp.async staging.
// ---------------------------------------------------------------------------
#define XROW (258 * 32)                   // 8256 B per halo row
#define XS_BYTES (6 * XROW)               // 49536 (6 halo rows for 4 out rows)
#define WS_BYTES (9 * 64 * 32)            // 18432
#define BUF_BYTES (XS_BYTES + WS_BYTES)   // 67968
#define SMEM_TOTAL (4096 + 2 * BUF_BYTES) // 140032

__device__ __forceinline__ unsigned sw(unsigned off) {
    return off ^ ((off & 128) >> 3);      // 32B-row swizzle (verified R4/R13/R15)
}
#define LDSM4(r, addr)                                                        \
    asm volatile("ldmatrix.sync.aligned.m8n8.x4.shared.b16 {%0,%1,%2,%3}, [%4];" \
                 : "=r"((r)[0]), "=r"((r)[1]), "=r"((r)[2]), "=r"((r)[3])     \
                 : "r"(addr))
#define CP16(dst, src, n)                                                     \
    asm volatile("cp.async.cg.shared.global [%0], [%1], 16, %2;"              \
                 :: "r"(dst), "l"(src), "r"(n))

__device__ __forceinline__ void mma_f16(float* d, const unsigned* a,
                                        unsigned b0, unsigned b1) {
    asm volatile(
        "mma.sync.aligned.m16n8k16.row.col.f32.f16.f16.f32 "
        "{%0,%1,%2,%3}, {%4,%5,%6,%7}, {%8,%9}, {%0,%1,%2,%3};\n"
        : "+f"(d[0]), "+f"(d[1]), "+f"(d[2]), "+f"(d[3])
        : "r"(a[0]), "r"(a[1]), "r"(a[2]), "r"(a[3]), "r"(b0), "r"(b1));
}

__global__ void __launch_bounds__(512, 1) conv_kernel(const float* __restrict__ bias,
                                                      float* __restrict__ out) {
    extern __shared__ unsigned char smem_raw[];
    const unsigned sbase = (unsigned)__cvta_generic_to_shared(smem_raw);
    float* Vs = (float*)smem_raw;                          // 4096 B (4 rows x 256)

    const int tid = threadIdx.x;
    const int warp = tid >> 5;
    const int lane = tid & 31;
    const int g = lane >> 2;
    const int t = lane & 3;
    const int wr = warp >> 2;          // output row within CTA (0..3)
    const int wc = warp & 3;           // 64-px quarter

    const int h0 = (blockIdx.x & 63) << 2;
    const int b = blockIdx.x >> 6;
    const int cout0 = blockIdx.y << 6;

    Vs[tid] = g_valid[((b << 8) + h0 + (tid >> 8)) * 256 + (tid & 255)];
    Vs[tid + 512] = g_valid[((b << 8) + h0 + 2 + (tid >> 8)) * 256 + (tid & 255)];

    // per-lane ldmatrix sub-offsets (32B rows)
    const unsigned a_lane = (lane & 15) * 32 + ((lane >> 4) << 4);
    const unsigned b_row = (lane & 7) + ((lane & 16) >> 1);  // x4 pair rows / rows+8
    const unsigned b_koff = (lane & 8) << 1;                 // k8-15 at +16B

    float acc[4][8][4];
#pragma unroll
    for (int mf = 0; mf < 4; ++mf)
#pragma unroll
        for (int nf = 0; nf < 8; ++nf)
#pragma unroll
            for (int i = 0; i < 4; ++i) acc[mf][nf][i] = 0.0f;

    // stage cin-chunk cc (16 halves) into buffer bi
    auto stage = [&](int cc, int bi) {
        const unsigned xb = sbase + 4096 + bi * BUF_BYTES;
        const unsigned wb = xb + XS_BYTES;
        for (int idx = tid; idx < 1152; idx += 512) {       // W: 9 taps x 64 m x 2 gran
            int gr = idx & 1;
            int m = (idx >> 1) & 63;
            int tap = idx >> 7;
            const __half* src = g_wt + (tap * COUT + cout0 + m) * CIN + cc * 16 + gr * 8;
            CP16(wb + sw(tap * 2048 + m * 32 + gr * 16), src, 16);
        }
        for (int idx = tid; idx < 3096; idx += 512) {       // X: 6 rows x 258 px x 2 gran
            int gr = idx & 1;
            int rp = idx >> 1;
            int p = rp % 258;
            int rr = rp / 258;
            int hh = h0 - 1 + rr;
            int iw = p - 1;
            bool ok = ((unsigned)hh < 256u) && ((unsigned)iw < 256u);
            const __half* src = g_xt
                + (((b << 8) + (ok ? hh : 0)) * 256 + (ok ? iw : 0)) * CIN
                + cc * 16 + gr * 8;
            CP16(xb + sw(rr * XROW + p * 32 + gr * 16), src, ok ? 16 : 0);
        }
        asm volatile("cp.async.commit_group;");
    };

    stage(0, 0);
    for (int cc = 0; cc < 12; ++cc) {
        if (cc < 11) {
            stage(cc + 1, (cc + 1) & 1);
            asm volatile("cp.async.wait_group 1;" ::: "memory");
        } else {
            asm volatile("cp.async.wait_group 0;" ::: "memory");
        }
        __syncthreads();

        const unsigned xb = sbase + 4096 + (cc & 1) * BUF_BYTES;
        const unsigned wb = xb + XS_BYTES;
#pragma unroll
        for (int tap = 0; tap < 9; ++tap) {
            const int kh = tap / 3;
            const int kw = tap - kh * 3;
            const int xrow = kh + wr;                       // halo row 0..5
            unsigned A[4][4];
#pragma unroll
            for (int mf = 0; mf < 4; ++mf)
                LDSM4(A[mf], wb + sw((unsigned)(tap * 2048 + mf * 512) + a_lane));
#pragma unroll
            for (int np = 0; np < 4; ++np) {                // nf pair 2np, 2np+1
                unsigned spb = (unsigned)(wc * 64 + np * 16 + kw) + b_row;
                unsigned r[4];
                LDSM4(r, xb + sw((unsigned)(xrow * XROW) + spb * 32 + b_koff));
#pragma unroll
                for (int mf = 0; mf < 4; ++mf) {
                    mma_f16(acc[mf][2 * np], A[mf], r[0], r[1]);
                    mma_f16(acc[mf][2 * np + 1], A[mf], r[2], r[3]);
                }
            }
        }
        __syncthreads();   // all warps done reading this buffer before restage
    }

    // epilogue: +bias, * validity, store fp32
    const int hrow = h0 + wr;
#pragma unroll
    for (int mf = 0; mf < 4; ++mf) {
        int m0 = cout0 + mf * 16 + g;
        float bz0 = bias[m0];
        float bz1 = bias[m0 + 8];
#pragma unroll
        for (int nf = 0; nf < 8; ++nf) {
            int n = (wc << 6) + (nf << 3) + 2 * t;
            float v0 = Vs[(wr << 8) + n];
            float v1 = Vs[(wr << 8) + n + 1];
            int o = ((b * COUT + m0) * 256 + hrow) * 256 + n;
            float2 r0, r1;
            r0.x = (acc[mf][nf][0] + bz0) * v0;
            r0.y = (acc[mf][nf][1] + bz0) * v1;
            *(float2*)(out + o) = r0;
            r1.x = (acc[mf][nf][2] + bz1) * v0;
            r1.y = (acc[mf][nf][3] + bz1) * v1;
            *(float2*)(out + o + 8 * 65536) = r1;
        }
    }
}

// ---------------------------------------------------------------------------
extern "C" void kernel_launch(void* const* d_in, const int* in_sizes, int n_in,
                              void* d_out, int out_size) {
    const float* x = (const float*)d_in[0];
    const int* mask = (const int*)d_in[1];
    const float* w = (const float*)d_in[2];
    const float* bias = (const float*)d_in[3];
    float* out = (float*)d_out;

    cudaFuncSetAttribute(conv_kernel, cudaFuncAttributeMaxDynamicSharedMemorySize,
                         SMEM_TOTAL);

    dim3 tg(4, 256, NB);
    cvt_x_kernel<<<tg, 256>>>(x);
    cvt_w_kernel<<<(COUT * CIN * 9 + 255) / 256, 256>>>(w);
    valid_kernel<<<(NB * 256 * 256 + 255) / 256, 256>>>(mask);

    dim3 grid(NB * 64, 3, 1);
    conv_kernel<<<grid, 512, SMEM_TOTAL>>>(bias, out);
}

// round 17
// speedup vs baseline: 2.9105x; 2.9105x over previous
#include <cuda_runtime.h>
#include <cuda_fp16.h>
#include <cstdint>

#define CIN 192
#define COUT 192
#define NB 4

// device scratch (sanctioned no-alloc workaround)
__device__ __align__(256) __half g_xt[NB * 256 * 256 * CIN];  // pixel-major [b][h][w][cin]
__device__ __align__(256) __half g_wt[9 * COUT * CIN];        // [tap][cout][cin]
__device__ __align__(256) float g_valid[NB * 256 * 256];

// ---------------------------------------------------------------------------
// Pass 1a: fp32 x [b][cin][h][w] -> fp16, pixel-major [b][h][w][cin]
// ---------------------------------------------------------------------------
#define TPS 200
__global__ void __launch_bounds__(256) cvt_x_kernel(const float* __restrict__ x) {
    __shared__ __half s[64 * TPS];
    const int tid = threadIdx.x;
    const int w0 = blockIdx.x << 6, h = blockIdx.y, b = blockIdx.z;
    const int wloc = tid & 63, cg = tid >> 6;
    const float* xb = x + ((b * CIN) * 256 + h) * 256 + w0;
    for (int ci = cg; ci < CIN; ci += 4)
        s[wloc * TPS + ci] = __float2half_rn(xb[ci * 65536 + wloc]);
    __syncthreads();
    int pixbase = ((b * 256 + h) * 256 + w0) * CIN;
    uint4* d = (uint4*)(g_xt + pixbase);
    for (int j = tid; j < 64 * 24; j += 256) {
        int p = j / 24, c = j % 24;
        d[j] = *(const uint4*)(s + p * TPS + c * 8);
    }
}

// ---------------------------------------------------------------------------
// Pass 1b: weight [cout][cin][kh][kw] -> tap-major [tap][cout][cin] fp16
// ---------------------------------------------------------------------------
__global__ void cvt_w_kernel(const float* __restrict__ w) {
    int i = blockIdx.x * blockDim.x + threadIdx.x;
    if (i >= COUT * CIN * 9) return;
    int kw = i % 3, kh = (i / 3) % 3, ci = (i / 9) % CIN, co = i / (9 * CIN);
    g_wt[((kh * 3 + kw) * COUT + co) * CIN + ci] = __float2half_rn(w[i]);
}

// ---------------------------------------------------------------------------
// Pass 1c: validity = 3x3 "any mask != 0" pool
// ---------------------------------------------------------------------------
__global__ void valid_kernel(const int* __restrict__ mask) {
    int i = blockIdx.x * blockDim.x + threadIdx.x;
    if (i >= NB * 256 * 256) return;
    int b = i >> 16, y = (i >> 8) & 255, x = i & 255;
    const int* mb = mask + (b << 16);
    int v = 0;
#pragma unroll
    for (int dy = -1; dy <= 1; ++dy) {
        int yy = y + dy;
        if (yy < 0 || yy > 255) continue;
#pragma unroll
        for (int dx = -1; dx <= 1; ++dx) {
            int xx = x + dx;
            if (xx < 0 || xx > 255) continue;
            v |= mb[yy * 256 + xx];
        }
    }
    g_valid[i] = (v != 0) ? 1.0f : 0.0f;
}

// ---------------------------------------------------------------------------
// Pass 2: implicit-GEMM conv, fp16 mma.sync m16n8k16, single pass.
// CTA = 64 cout x 2 output rows x 128 px; 2 CTAs/SM (regs<=128).
// 3-stage cp.async pipeline, ONE __syncthreads per chunk:
//   wait(group cc) ; sync ; stage(cc+2 -> buf[(cc+2)%3]) ; compute(cc)
// (buf[(cc+2)%3]'s last readers were compute(cc-1), fenced by this sync.)
// ---------------------------------------------------------------------------
#define XROW (132 * 32)                   // 4224 B per halo row (130 used)
#define XS_BYTES (4 * XROW)               // 16896
#define WS_BYTES (9 * 64 * 32)            // 18432
#define BUF_BYTES (XS_BYTES + WS_BYTES)   // 35328 (= 138*256, keeps 256B align)
#define SMEM_TOTAL (1024 + 3 * BUF_BYTES) // 107008 -> 2 CTAs/SM (214016 < 228K)

__device__ __forceinline__ unsigned sw(unsigned off) {
    return off ^ ((off & 128) >> 3);      // 32B-row swizzle (verified R4/R13/R15)
}
#define LDSM4(r, addr)                                                        \
    asm volatile("ldmatrix.sync.aligned.m8n8.x4.shared.b16 {%0,%1,%2,%3}, [%4];" \
                 : "=r"((r)[0]), "=r"((r)[1]), "=r"((r)[2]), "=r"((r)[3])     \
                 : "r"(addr))
#define CP16(dst, src, n)                                                     \
    asm volatile("cp.async.cg.shared.global [%0], [%1], 16, %2;"              \
                 :: "r"(dst), "l"(src), "r"(n))

__device__ __forceinline__ void mma_f16(float* d, const unsigned* a,
                                        unsigned b0, unsigned b1) {
    asm volatile(
        "mma.sync.aligned.m16n8k16.row.col.f32.f16.f16.f32 "
        "{%0,%1,%2,%3}, {%4,%5,%6,%7}, {%8,%9}, {%0,%1,%2,%3};\n"
        : "+f"(d[0]), "+f"(d[1]), "+f"(d[2]), "+f"(d[3])
        : "r"(a[0]), "r"(a[1]), "r"(a[2]), "r"(a[3]), "r"(b0), "r"(b1));
}

__global__ void __launch_bounds__(256, 2) conv_kernel(const float* __restrict__ bias,
                                                      float* __restrict__ out) {
    extern __shared__ unsigned char smem_raw[];
    const unsigned sbase = (unsigned)__cvta_generic_to_shared(smem_raw);
    float* Vs = (float*)smem_raw;                          // 1024 B (2 rows x 128)

    const int tid = threadIdx.x;
    const int warp = tid >> 5;
    const int lane = tid & 31;
    const int g = lane >> 2;
    const int t = lane & 3;
    const int wr = warp >> 2;          // output row within CTA (0/1)
    const int wc = warp & 3;           // 32-px quarter of the 128-px half

    const int wh = blockIdx.x & 1;     // which 128-px half of the row
    const int w0 = wh << 7;
    const int h0 = ((blockIdx.x >> 1) & 127) << 1;
    const int b = blockIdx.x >> 8;
    const int cout0 = blockIdx.y << 6;

    Vs[tid] = g_valid[((b << 8) + h0 + (tid >> 7)) * 256 + w0 + (tid & 127)];

    // per-lane ldmatrix sub-offsets (32B rows)
    const unsigned a_lane = (lane & 15) * 32 + ((lane >> 4) << 4);
    const unsigned b_row = (lane & 7) + ((lane & 16) >> 1);  // x4 pair rows / rows+8
    const unsigned b_koff = (lane & 8) << 1;                 // k8-15 at +16B

    float acc[4][4][4];
#pragma unroll
    for (int mf = 0; mf < 4; ++mf)
#pragma unroll
        for (int nf = 0; nf < 4; ++nf)
#pragma unroll
            for (int i = 0; i < 4; ++i) acc[mf][nf][i] = 0.0f;

    // stage cin-chunk cc (16 halves) into buffer bi
    auto stage = [&](int cc, int bi) {
        const unsigned xb = sbase + 1024 + bi * BUF_BYTES;
        const unsigned wb = xb + XS_BYTES;
        for (int idx = tid; idx < 1152; idx += 256) {       // W: 9 taps x 64 m x 2 gran
            int gr = idx & 1;
            int m = (idx >> 1) & 63;
            int tap = idx >> 7;
            const __half* src = g_wt + (tap * COUT + cout0 + m) * CIN + cc * 16 + gr * 8;
            CP16(wb + sw(tap * 2048 + m * 32 + gr * 16), src, 16);
        }
        for (int idx = tid; idx < 1040; idx += 256) {       // X: 4 rows x 130 px x 2 gran
            int gr = idx & 1;
            int rp = idx >> 1;
            int p = rp % 130;
            int rr = rp / 130;
            int hh = h0 - 1 + rr;
            int iw = w0 - 1 + p;
            bool ok = ((unsigned)hh < 256u) && ((unsigned)iw < 256u);
            const __half* src = g_xt
                + (((b << 8) + (ok ? hh : 0)) * 256 + (ok ? iw : 0)) * CIN
                + cc * 16 + gr * 8;
            CP16(xb + sw(rr * XROW + p * 32 + gr * 16), src, ok ? 16 : 0);
        }
        asm volatile("cp.async.commit_group;");
    };

    stage(0, 0);
    stage(1, 1);
    int bi2 = 2;                                            // buffer of chunk cc+2
    for (int cc = 0; cc < 12; ++cc) {
        if (cc < 11) asm volatile("cp.async.wait_group 1;" ::: "memory");
        else         asm volatile("cp.async.wait_group 0;" ::: "memory");
        __syncthreads();   // all warps: chunk cc ready AND compute(cc-1) done
        if (cc < 10) {
            stage(cc + 2, bi2);
            bi2 = (bi2 == 2) ? 0 : bi2 + 1;
        }

        const unsigned xb = sbase + 1024 + (cc % 3) * BUF_BYTES;
        const unsigned wb = xb + XS_BYTES;
#pragma unroll
        for (int tap = 0; tap < 9; ++tap) {
            const int kh = tap / 3;
            const int kw = tap - kh * 3;
            const int xrow = kh + wr;                       // halo row for this warp
            unsigned A[4][4];
#pragma unroll
            for (int mf = 0; mf < 4; ++mf)
                LDSM4(A[mf], wb + sw((unsigned)(tap * 2048 + mf * 512) + a_lane));
#pragma unroll
            for (int np = 0; np < 2; ++np) {                // nf pair 2np, 2np+1
                unsigned spb = (unsigned)(wc * 32 + np * 16 + kw) + b_row;
                unsigned r[4];
                LDSM4(r, xb + sw((unsigned)(xrow * XROW) + spb * 32 + b_koff));
#pragma unroll
                for (int mf = 0; mf < 4; ++mf) {
                    mma_f16(acc[mf][2 * np], A[mf], r[0], r[1]);
                    mma_f16(acc[mf][2 * np + 1], A[mf], r[2], r[3]);
                }
            }
        }
    }

    // epilogue: +bias, * validity, store fp32
    const int hrow = h0 + wr;
#pragma unroll
    for (int mf = 0; mf < 4; ++mf) {
        int m0 = cout0 + mf * 16 + g;
        float bz0 = bias[m0];
        float bz1 = bias[m0 + 8];
#pragma unroll
        for (int nf = 0; nf < 4; ++nf) {
            int n = (wc << 5) + (nf << 3) + 2 * t;
            float v0 = Vs[(wr << 7) + n];
            float v1 = Vs[(wr << 7) + n + 1];
            int o = ((b * COUT + m0) * 256 + hrow) * 256 + w0 + n;
            float2 r0, r1;
            r0.x = (acc[mf][nf][0] + bz0) * v0;
            r0.y = (acc[mf][nf][1] + bz0) * v1;
            *(float2*)(out + o) = r0;
            r1.x = (acc[mf][nf][2] + bz1) * v0;
            r1.y = (acc[mf][nf][3] + bz1) * v1;
            *(float2*)(out + o + 8 * 65536) = r1;
        }
    }
}

// ---------------------------------------------------------------------------
extern "C" void kernel_launch(void* const* d_in, const int* in_sizes, int n_in,
                              void* d_out, int out_size) {
    const float* x = (const float*)d_in[0];
    const int* mask = (const int*)d_in[1];
    const float* w = (const float*)d_in[2];
    const float* bias = (const float*)d_in[3];
    float* out = (float*)d_out;

    cudaFuncSetAttribute(conv_kernel, cudaFuncAttributeMaxDynamicSharedMemorySize,
                         SMEM_TOTAL);

    dim3 tg(4, 256, NB);
    cvt_x_kernel<<<tg, 256>>>(x);
    cvt_w_kernel<<<(COUT * CIN * 9 + 255) / 256, 256>>>(w);
    valid_kernel<<<(NB * 256 * 256 + 255) / 256, 256>>>(mask);

    dim3 grid(NB * 256, 3, 1);
    conv_kernel<<<grid, 256, SMEM_TOTAL>>>(bias, out);
}